// round 1
// baseline (speedup 1.0000x reference)
#include <cuda_runtime.h>
#include <math.h>

#define IN_COUNT   256
#define OUT_COUNT  256
#define BATCH      2048
#define TB         8          // batches per block
#define N_SPLINES  5
#define N_INTERVALS 16

// Precomputed per-(o,i) parameters, stored transposed [i][o] for coalesced
// access by the main kernel (thread = output o).
//   g_p4[i*OUT+o] = {C3, C4, C2, CA},  g_p5[i*OUT+o] = C5
__device__ float4 g_p4[IN_COUNT * OUT_COUNT];
__device__ float  g_p5[IN_COUNT * OUT_COUNT];

__device__ __forceinline__ float ex2f_(float x) {
    float r; asm("ex2.approx.ftz.f32 %0, %1;" : "=f"(r) : "f"(x)); return r;
}
__device__ __forceinline__ float lg2f_(float x) {
    float r; asm("lg2.approx.ftz.f32 %0, %1;" : "=f"(r) : "f"(x)); return r;
}

// ---------------------------------------------------------------------------
// Kernel 1: evaluate the 5 piecewise cubics at w_norm[o,i], fold constants.
// 65536 threads; completely off the critical path (~µs).
// ---------------------------------------------------------------------------
__global__ void KAN_precompute_kernel(const float* __restrict__ w,
                                      const float* __restrict__ raw_gamma,
                                      const float* __restrict__ breaks,
                                      const float* __restrict__ coefs,
                                      const float* __restrict__ mu_p,
                                      const float* __restrict__ sigma_p)
{
    int e = blockIdx.x * blockDim.x + threadIdx.x;
    if (e >= IN_COUNT * OUT_COUNT) return;
    int o = e >> 8;          // e / IN_COUNT
    int i = e & 255;         // e % IN_COUNT

    float mu = *mu_p, sigma = *sigma_p;
    float wv = w[e];         // w is [OUT, IN], e = o*IN + i
    float wn = (fminf(fmaxf(wv, 5.5f), 35.5f) - mu) / sigma;

    float b[N_SPLINES];
    #pragma unroll
    for (int s = 0; s < N_SPLINES; ++s) {
        const float* br = breaks + s * (N_INTERVALS + 1);
        float wc = fminf(fmaxf(wn, br[0]), br[N_INTERVALS] - 1e-6f);
        // searchsorted(side='right') - 1 == count of breaks[k] <= wc, minus
        // the always-true k=0, clamped to N_INTERVALS-1. Exact comparisons
        // against the actual break values (no float-division index tricks).
        int idx = 0;
        #pragma unroll
        for (int k = 1; k <= N_INTERVALS; ++k) idx += (wc >= br[k]) ? 1 : 0;
        if (idx > N_INTERVALS - 1) idx = N_INTERVALS - 1;
        const float* a = coefs + (s * N_INTERVALS + idx) * 4;
        float t = wc - br[idx];
        b[s] = ((a[0] * t + a[1]) * t + a[2]) * t + a[3];
    }

    // gamma = softplus(raw_gamma) / OUT_COUNT  (stable softplus)
    float rg = raw_gamma[e];
    float g = (fmaxf(rg, 0.0f) + log1pf(expf(-fabsf(rg)))) * (1.0f / OUT_COUNT);

    const float LOG2E = 1.4426950408889634f;
    const float LN2   = 0.6931471805599453f;

    // y_ = b1*log1p(b2*log1p((e^{b3 x}-1)^{b4})) + b5*x, all in log2 domain:
    //   base = 2^{C3 x} - 1,  p = 2^{C4 * log2(base)},
    //   term = CA * log2(1 + C2 * log2(1 + p)) + C5 * x
    float4 P;
    P.x = b[2] * LOG2E;        // C3 = b3 * log2(e)
    P.y = b[3];                // C4 = b4
    P.z = b[1] * LN2;          // C2 = b2 * ln2
    P.w = b[0] * g * LN2;      // CA = b1 * g * ln2
    int te = i * OUT_COUNT + o;
    g_p4[te] = P;
    g_p5[te] = b[4] * g;       // C5 = b5 * g
}

// ---------------------------------------------------------------------------
// Kernel 2: main elementwise + reduce. Thread = output o, TB batches each.
// All lanes of a warp share the same x value per (t,i), so the x>0 test is
// warp-uniform: a taken skip-branch removes the 5 MUFU ops for ~50% of
// elements with zero divergence.
// ---------------------------------------------------------------------------
__global__ __launch_bounds__(256) void KAN_main_kernel(
        const float* __restrict__ x, float* __restrict__ out)
{
    __shared__ float xs[TB][IN_COUNT];

    const int o  = threadIdx.x;
    const int b0 = blockIdx.x * TB;

    // Stage relu(x) tile: coalesced global reads, stride-1 shared writes.
    for (int idx = threadIdx.x; idx < TB * IN_COUNT; idx += 256) {
        xs[idx >> 8][idx & 255] = fmaxf(x[b0 * IN_COUNT + idx], 0.0f);
    }
    __syncthreads();

    float acc[TB];
    #pragma unroll
    for (int t = 0; t < TB; ++t) acc[t] = 0.0f;

    // Software prefetch of next i's params to hide L2 latency.
    float4 P  = g_p4[o];
    float  c5 = g_p5[o];

    for (int i = 0; i < IN_COUNT; ++i) {
        float4 Pn;
        float  c5n;
        int inext = (i + 1 < IN_COUNT) ? (i + 1) : i;
        Pn  = g_p4[inext * OUT_COUNT + o];
        c5n = g_p5[inext * OUT_COUNT + o];

        #pragma unroll
        for (int t = 0; t < TB; ++t) {
            float xv = xs[t][i];
            if (xv > 0.0f) {                       // warp-uniform skip
                float e    = ex2f_(P.x * xv);      // 2^{C3 x}
                float base = e - 1.0f;
                float p    = ex2f_(P.y * lg2f_(base));      // base^{b4}
                float t2   = lg2f_(1.0f + p);               // log2(1+p)
                float u2   = lg2f_(fmaf(P.z, t2, 1.0f));    // log2(1+C2 t2)
                acc[t] = fmaf(P.w, u2, fmaf(c5, xv, acc[t]));
            }
        }
        P  = Pn;
        c5 = c5n;
    }

    #pragma unroll
    for (int t = 0; t < TB; ++t) {
        float y  = acc[t];
        float sp = fmaxf(y, 0.0f) + log1pf(expf(-fabsf(y)));  // softplus
        out[(b0 + t) * OUT_COUNT + o] = sp;
    }
}

// ---------------------------------------------------------------------------
// Inputs (metadata order): x, w, raw_gamma, breaks, coefs, mu, sigma.
// Output: float32 [BATCH, OUT_COUNT].
// ---------------------------------------------------------------------------
extern "C" void kernel_launch(void* const* d_in, const int* in_sizes, int n_in,
                              void* d_out, int out_size)
{
    const float* x      = (const float*)d_in[0];
    const float* w      = (const float*)d_in[1];
    const float* rgam   = (const float*)d_in[2];
    const float* breaks = (const float*)d_in[3];
    const float* coefs  = (const float*)d_in[4];
    const float* mu     = (const float*)d_in[5];
    const float* sigma  = (const float*)d_in[6];

    KAN_precompute_kernel<<<(IN_COUNT * OUT_COUNT + 255) / 256, 256>>>(
        w, rgam, breaks, coefs, mu, sigma);

    KAN_main_kernel<<<BATCH / TB, 256>>>(x, (float*)d_out);
}

// round 2
// speedup vs baseline: 1.5812x; 1.5812x over previous
#include <cuda_runtime.h>
#include <math.h>

#define IN_COUNT    256
#define OUT_COUNT   256
#define BATCH       2048
#define TB          8           // batches per block
#define ISPLIT      4           // blocks cooperating on the i-reduction
#define ITILE       (IN_COUNT / ISPLIT)   // 64 i's per block
#define N_SPLINES   5
#define N_INTERVALS 16

// Precomputed per-(o,i) parameters, transposed [i][o] for coalesced access.
__device__ float4 g_p4[IN_COUNT * OUT_COUNT];
__device__ float  g_p5[IN_COUNT * OUT_COUNT];
// Deterministic partial sums: [isplit][batch][out]  (8 MB)
__device__ float  g_partial[ISPLIT * BATCH * OUT_COUNT];

__device__ __forceinline__ float ex2f_(float x) {
    float r; asm("ex2.approx.ftz.f32 %0, %1;" : "=f"(r) : "f"(x)); return r;
}
__device__ __forceinline__ float lg2f_(float x) {
    float r; asm("lg2.approx.ftz.f32 %0, %1;" : "=f"(r) : "f"(x)); return r;
}

// ---------------------------------------------------------------------------
// Kernel 1: spline eval + constant folding (off critical path).
// ---------------------------------------------------------------------------
__global__ void KAN_precompute_kernel(const float* __restrict__ w,
                                      const float* __restrict__ raw_gamma,
                                      const float* __restrict__ breaks,
                                      const float* __restrict__ coefs,
                                      const float* __restrict__ mu_p,
                                      const float* __restrict__ sigma_p)
{
    int e = blockIdx.x * blockDim.x + threadIdx.x;
    if (e >= IN_COUNT * OUT_COUNT) return;
    int o = e >> 8;
    int i = e & 255;

    float mu = *mu_p, sigma = *sigma_p;
    float wv = w[e];
    float wn = (fminf(fmaxf(wv, 5.5f), 35.5f) - mu) / sigma;

    float b[N_SPLINES];
    #pragma unroll
    for (int s = 0; s < N_SPLINES; ++s) {
        const float* br = breaks + s * (N_INTERVALS + 1);
        float wc = fminf(fmaxf(wn, br[0]), br[N_INTERVALS] - 1e-6f);
        int idx = 0;
        #pragma unroll
        for (int k = 1; k <= N_INTERVALS; ++k) idx += (wc >= br[k]) ? 1 : 0;
        if (idx > N_INTERVALS - 1) idx = N_INTERVALS - 1;
        const float* a = coefs + (s * N_INTERVALS + idx) * 4;
        float t = wc - br[idx];
        b[s] = ((a[0] * t + a[1]) * t + a[2]) * t + a[3];
    }

    float rg = raw_gamma[e];
    float g = (fmaxf(rg, 0.0f) + log1pf(expf(-fabsf(rg)))) * (1.0f / OUT_COUNT);

    const float LOG2E = 1.4426950408889634f;
    const float LN2   = 0.6931471805599453f;

    float4 P;
    P.x = b[2] * LOG2E;        // C3
    P.y = b[3];                // C4
    P.z = b[1] * LN2;          // C2
    P.w = b[0] * g * LN2;      // CA
    int te = i * OUT_COUNT + o;
    g_p4[te] = P;
    g_p5[te] = b[4] * g;       // C5
}

// ---------------------------------------------------------------------------
// Kernel 2: main compute. blockIdx.x = batch tile, blockIdx.y = i-split.
// Thread = output o; TB batches; ITILE=64 inputs. Warp-uniform x>0 skip.
// Partial sums written deterministically to g_partial.
// ---------------------------------------------------------------------------
__global__ __launch_bounds__(256) void KAN_main_kernel(
        const float* __restrict__ x)
{
    __shared__ float xs[TB][ITILE];

    const int o  = threadIdx.x;
    const int b0 = blockIdx.x * TB;
    const int i0 = blockIdx.y * ITILE;

    // Stage relu(x) slice: TB*ITILE = 512 elements, 2 per thread.
    for (int idx = threadIdx.x; idx < TB * ITILE; idx += 256) {
        int t = idx / ITILE, i = idx % ITILE;
        xs[t][i] = fmaxf(x[(b0 + t) * IN_COUNT + i0 + i], 0.0f);
    }
    __syncthreads();

    float acc[TB];
    #pragma unroll
    for (int t = 0; t < TB; ++t) acc[t] = 0.0f;

    const float4* __restrict__ p4 = g_p4 + i0 * OUT_COUNT + o;
    const float*  __restrict__ p5 = g_p5 + i0 * OUT_COUNT + o;

    float4 P  = p4[0];
    float  c5 = p5[0];

    for (int i = 0; i < ITILE; ++i) {
        int inx = (i + 1 < ITILE) ? (i + 1) : i;
        float4 Pn  = p4[inx * OUT_COUNT];
        float  c5n = p5[inx * OUT_COUNT];

        #pragma unroll
        for (int t = 0; t < TB; ++t) {
            float xv = xs[t][i];
            if (xv > 0.0f) {                       // warp-uniform skip
                float e    = ex2f_(P.x * xv);               // 2^{C3 x}
                float base = e - 1.0f;
                float p    = ex2f_(P.y * lg2f_(base));      // base^{b4}
                float t2   = lg2f_(1.0f + p);
                float u2   = lg2f_(fmaf(P.z, t2, 1.0f));
                acc[t] = fmaf(P.w, u2, fmaf(c5, xv, acc[t]));
            }
        }
        P  = Pn;
        c5 = c5n;
    }

    float* dst = g_partial + (size_t)blockIdx.y * (BATCH * OUT_COUNT)
                 + b0 * OUT_COUNT + o;
    #pragma unroll
    for (int t = 0; t < TB; ++t)
        dst[t * OUT_COUNT] = acc[t];
}

// ---------------------------------------------------------------------------
// Kernel 3: combine ISPLIT partials + final softplus.
// ---------------------------------------------------------------------------
__global__ __launch_bounds__(256) void KAN_combine_kernel(float* __restrict__ out)
{
    int idx = blockIdx.x * blockDim.x + threadIdx.x;
    if (idx >= BATCH * OUT_COUNT) return;
    float y = 0.0f;
    #pragma unroll
    for (int s = 0; s < ISPLIT; ++s)
        y += g_partial[s * (BATCH * OUT_COUNT) + idx];
    out[idx] = fmaxf(y, 0.0f) + log1pf(expf(-fabsf(y)));
}

// ---------------------------------------------------------------------------
// Inputs: x, w, raw_gamma, breaks, coefs, mu, sigma. Output fp32 [B, O].
// ---------------------------------------------------------------------------
extern "C" void kernel_launch(void* const* d_in, const int* in_sizes, int n_in,
                              void* d_out, int out_size)
{
    const float* x      = (const float*)d_in[0];
    const float* w      = (const float*)d_in[1];
    const float* rgam   = (const float*)d_in[2];
    const float* breaks = (const float*)d_in[3];
    const float* coefs  = (const float*)d_in[4];
    const float* mu     = (const float*)d_in[5];
    const float* sigma  = (const float*)d_in[6];

    KAN_precompute_kernel<<<(IN_COUNT * OUT_COUNT + 255) / 256, 256>>>(
        w, rgam, breaks, coefs, mu, sigma);

    dim3 grid(BATCH / TB, ISPLIT);
    KAN_main_kernel<<<grid, 256>>>(x);

    KAN_combine_kernel<<<(BATCH * OUT_COUNT + 255) / 256, 256>>>((float*)d_out);
}